// round 2
// baseline (speedup 1.0000x reference)
#include <cuda_runtime.h>
#include <math.h>

// Problem constants (fixed by the reference)
#define NB 4
#define NS 2048
#define ND 512
#define NH 8
#define NDK 64
#define SCL 0.125f          // 1/sqrt(64)
#define NEGBIG (-1e30f)

// Scratch (static device allocations — allowed)
__device__ float g_Q[(size_t)NB * NH * NS * NDK];   // [b,h,s,dk]
__device__ float g_K[(size_t)NB * NH * NS * NDK];
__device__ float g_V[(size_t)NB * NH * NS * NDK];
__device__ float g_Ctx[(size_t)NB * NS * ND];       // [b,s,h*dk]
__device__ float g_M[(size_t)NB * NH * NS];         // row max
__device__ float g_Z[(size_t)NB * NH * NS];         // row sum
__device__ float g_madd[(size_t)NB * NS];           // 0 / -inf additive mask
__device__ int   g_maskkind;

// ---------------------------------------------------------------------------
// Mask dtype sniffing: the harness's dtype for a bool input is undocumented.
// Byte statistics over the first 8192 bytes distinguish u8/i32/f32/bf16
// deterministically for a ~90%-true mask.
// ---------------------------------------------------------------------------
__global__ void mask_detect(const unsigned char* __restrict__ mraw) {
    __shared__ int s_not01, s_oneOther, s_3fOdd;
    if (threadIdx.x == 0) { s_not01 = 0; s_oneOther = 0; s_3fOdd = 0; }
    __syncthreads();
    int l_not01 = 0, l_oneOther = 0, l_3fOdd = 0;
    for (int i = threadIdx.x; i < NB * NS; i += blockDim.x) {
        const unsigned char v = mraw[i];
        if (v > 1) l_not01++;
        if (v == 1 && (i & 3) != 0) l_oneOther++;
        if (v == 0x3f && (i & 3) == 1) l_3fOdd++;   // bf16 1.0 = 0x80,0x3f pairs
    }
    atomicAdd(&s_not01, l_not01);
    atomicAdd(&s_oneOther, l_oneOther);
    atomicAdd(&s_3fOdd, l_3fOdd);
    __syncthreads();
    if (threadIdx.x == 0) {
        int kind;
        if (s_not01 > 0)        kind = (s_3fOdd > 0) ? 3 : 2;  // bf16 : f32
        else if (s_oneOther == 0) kind = 1;                    // i32 (ones only at %4==0)
        else                    kind = 0;                      // u8/bool
        g_maskkind = kind;
    }
}

__global__ void mask_convert(const void* __restrict__ mraw) {
    const int i = blockIdx.x * blockDim.x + threadIdx.x;
    if (i >= NB * NS) return;
    const int kind = g_maskkind;
    bool on;
    if (kind == 0)      on = ((const unsigned char*)mraw)[i] != 0;
    else if (kind == 1) on = ((const int*)mraw)[i] != 0;
    else if (kind == 2) on = ((const float*)mraw)[i] != 0.f;
    else                on = ((const unsigned short*)mraw)[i] != 0;
    g_madd[i] = on ? 0.f : -INFINITY;
}

// ---------------------------------------------------------------------------
// C[m,n] = sum_k X[m,k] * W[n,k] + bias[n]
// MODE 0: write head-split layout [b,h,s,dk]; MODE 1: flat [m, n]
// ---------------------------------------------------------------------------
template <int MODE>
__global__ __launch_bounds__(256) void gemm_xwt(const float* __restrict__ X,
                                                const float* __restrict__ W,
                                                const float* __restrict__ bias,
                                                float* __restrict__ Y) {
    __shared__ float As[16][68];
    __shared__ float Bs[16][68];
    const int tid = threadIdx.x;
    const int tx = tid & 15, ty = tid >> 4;
    const int m0 = blockIdx.y * 64, n0 = blockIdx.x * 64;
    const int lk = tid & 15, lr = tid >> 4;

    float acc[4][4] = {};
    for (int k0 = 0; k0 < ND; k0 += 16) {
#pragma unroll
        for (int r = 0; r < 4; r++) {
            As[lk][lr + 16 * r] = X[(size_t)(m0 + lr + 16 * r) * ND + k0 + lk];
            Bs[lk][lr + 16 * r] = W[(size_t)(n0 + lr + 16 * r) * ND + k0 + lk];
        }
        __syncthreads();
#pragma unroll
        for (int kk = 0; kk < 16; kk++) {
            float4 a = *(const float4*)&As[kk][4 * ty];
            float4 b = *(const float4*)&Bs[kk][4 * tx];
            float av[4] = {a.x, a.y, a.z, a.w};
            float bv[4] = {b.x, b.y, b.z, b.w};
#pragma unroll
            for (int i = 0; i < 4; i++)
#pragma unroll
                for (int j = 0; j < 4; j++) acc[i][j] += av[i] * bv[j];
        }
        __syncthreads();
    }

#pragma unroll
    for (int i = 0; i < 4; i++) {
        const int m = m0 + 4 * ty + i;
#pragma unroll
        for (int j = 0; j < 4; j++) {
            const int n = n0 + 4 * tx + j;
            float v = acc[i][j] + bias[n];
            if (MODE == 0) {
                const int b = m >> 11, s = m & (NS - 1);
                const int h = n >> 6, jd = n & 63;
                Y[(((size_t)(b * NH + h)) * NS + s) * NDK + jd] = v;
            } else {
                Y[(size_t)m * ND + n] = v;
            }
        }
    }
}

// ---------------------------------------------------------------------------
// Flash attention per (b,h,q-tile=64). Online softmax, stores O, m, Z.
// ---------------------------------------------------------------------------
__global__ __launch_bounds__(256) void flash_attn(const float* __restrict__ maddg,
                                                  const float* __restrict__ Qg,
                                                  const float* __restrict__ Kg,
                                                  const float* __restrict__ Vg,
                                                  float* __restrict__ Og,
                                                  float* __restrict__ Mg,
                                                  float* __restrict__ Zg) {
    extern __shared__ float sm[];
    float(*Qs)[68] = (float(*)[68])sm;                 // [d][q]
    float(*Ks)[68] = (float(*)[68])(sm + 64 * 68);     // [d][k]
    float(*Vs)[68] = (float(*)[68])(sm + 2 * 64 * 68); // [k][d]
    float(*Ps)[68] = (float(*)[68])(sm + 3 * 64 * 68); // [k][q]
    __shared__ float madd[64];

    const int tid = threadIdx.x;
    const int tx = tid & 15, ty = tid >> 4;
    const int bh = blockIdx.y;
    const int b = bh >> 3, h = bh & 7;
    const int q0 = blockIdx.x * 64;
    const float* Q = Qg + (size_t)bh * NS * NDK;
    const float* K = Kg + (size_t)bh * NS * NDK;
    const float* V = Vg + (size_t)bh * NS * NDK;

    {   // load Q tile transposed: Qs[d][q]
        const int d = tid & 63, r = tid >> 6;
#pragma unroll
        for (int p = 0; p < 16; p++) {
            const int qq = p * 4 + r;
            Qs[d][qq] = Q[(size_t)(q0 + qq) * NDK + d];
        }
    }
    __syncthreads();

    float Ofr[4][4] = {};
    float mI[4], zI[4];
#pragma unroll
    for (int i = 0; i < 4; i++) { mI[i] = -INFINITY; zI[i] = 0.f; }

    for (int kt = 0; kt < NS; kt += 64) {
        {   // load K tile transposed, V tile natural, mask tile
            const int d = tid & 63, r = tid >> 6;
#pragma unroll
            for (int p = 0; p < 16; p++) {
                const int kk = p * 4 + r;
                Ks[d][kk] = K[(size_t)(kt + kk) * NDK + d];
                Vs[kk][d] = V[(size_t)(kt + kk) * NDK + d];
            }
            if (tid < 64) madd[tid] = maddg[b * NS + kt + tid];
        }
        __syncthreads();

        // ---- QK^T tile ----
        float sfr[4][4] = {};
#pragma unroll 16
        for (int kk = 0; kk < 64; kk++) {
            float4 a = *(const float4*)&Qs[kk][4 * ty];
            float4 bk4 = *(const float4*)&Ks[kk][4 * tx];
            float av[4] = {a.x, a.y, a.z, a.w};
            float bv[4] = {bk4.x, bk4.y, bk4.z, bk4.w};
#pragma unroll
            for (int i = 0; i < 4; i++)
#pragma unroll
                for (int j = 0; j < 4; j++) sfr[i][j] += av[i] * bv[j];
        }

        // ---- online softmax update ----
#pragma unroll
        for (int i = 0; i < 4; i++) {
#pragma unroll
            for (int j = 0; j < 4; j++) sfr[i][j] = sfr[i][j] * SCL + madd[4 * tx + j];
            float rm = fmaxf(fmaxf(sfr[i][0], sfr[i][1]), fmaxf(sfr[i][2], sfr[i][3]));
#pragma unroll
            for (int off = 8; off > 0; off >>= 1)
                rm = fmaxf(rm, __shfl_xor_sync(0xffffffffu, rm, off));
            const float mn = fmaxf(mI[i], rm);
            const float alpha = (mI[i] <= NEGBIG) ? 0.f : expf(mI[i] - mn);
            float pv[4];
            float rs = 0.f;
#pragma unroll
            for (int j = 0; j < 4; j++) {
                const float p = (sfr[i][j] <= NEGBIG) ? 0.f : expf(sfr[i][j] - mn);
                pv[j] = p;
                rs += p;
            }
#pragma unroll
            for (int off = 8; off > 0; off >>= 1)
                rs += __shfl_xor_sync(0xffffffffu, rs, off);
            zI[i] = zI[i] * alpha + rs;
            mI[i] = mn;
#pragma unroll
            for (int j = 0; j < 4; j++) {
                Ofr[i][j] *= alpha;
                Ps[4 * tx + j][4 * ty + i] = pv[j];
            }
        }
        __syncthreads();

        // ---- P @ V ----
#pragma unroll 16
        for (int kk = 0; kk < 64; kk++) {
            float4 p4 = *(const float4*)&Ps[kk][4 * ty];
            float4 v4 = *(const float4*)&Vs[kk][4 * tx];
            float pvv[4] = {p4.x, p4.y, p4.z, p4.w};
            float vv[4] = {v4.x, v4.y, v4.z, v4.w};
#pragma unroll
            for (int i = 0; i < 4; i++)
#pragma unroll
                for (int j = 0; j < 4; j++) Ofr[i][j] += pvv[i] * vv[j];
        }
        __syncthreads();
    }

    // epilogue: normalize, write O + stats
#pragma unroll
    for (int i = 0; i < 4; i++) {
        const float inv = (zI[i] > 0.f) ? 1.f / zI[i] : 0.f;
        const int qq = q0 + 4 * ty + i;
        float4 o4 = make_float4(Ofr[i][0] * inv, Ofr[i][1] * inv,
                                Ofr[i][2] * inv, Ofr[i][3] * inv);
        *(float4*)&Og[((size_t)(b * NS + qq)) * ND + h * NDK + 4 * tx] = o4;
        if (tx == 0) {
            Mg[(size_t)bh * NS + qq] = mI[i];
            Zg[(size_t)bh * NS + qq] = zI[i];
        }
    }
}

// ---------------------------------------------------------------------------
// attn.mean(axis=heads): recompute scores per (b, q-tile, k-tile) over all h,
// use stored (m, Z) to form exact softmax probabilities, write mean once.
// ---------------------------------------------------------------------------
__global__ __launch_bounds__(256) void attn_mean_k(const float* __restrict__ maddg,
                                                   const float* __restrict__ Qg,
                                                   const float* __restrict__ Kg,
                                                   const float* __restrict__ Mg,
                                                   const float* __restrict__ Zg,
                                                   float* __restrict__ out) {
    __shared__ float Qs[64][68];
    __shared__ float Ks[64][68];
    __shared__ float madd[64];
    const int tid = threadIdx.x;
    const int tx = tid & 15, ty = tid >> 4;
    const int b = blockIdx.z;
    const int q0 = blockIdx.y * 64, k0 = blockIdx.x * 64;
    if (tid < 64) madd[tid] = maddg[b * NS + k0 + tid];

    float acc[4][4] = {};
    for (int h = 0; h < NH; h++) {
        __syncthreads();
        const float* Q = Qg + ((size_t)(b * NH + h)) * NS * NDK;
        const float* K = Kg + ((size_t)(b * NH + h)) * NS * NDK;
        {
            const int d = tid & 63, r = tid >> 6;
#pragma unroll
            for (int p = 0; p < 16; p++) {
                const int rr = p * 4 + r;
                Qs[d][rr] = Q[(size_t)(q0 + rr) * NDK + d];
                Ks[d][rr] = K[(size_t)(k0 + rr) * NDK + d];
            }
        }
        __syncthreads();

        float mrow[4], zinv[4];
#pragma unroll
        for (int i = 0; i < 4; i++) {
            const size_t idx = ((size_t)(b * NH + h)) * NS + q0 + 4 * ty + i;
            mrow[i] = Mg[idx];
            const float z = Zg[idx];
            zinv[i] = (z > 0.f) ? 1.f / z : 0.f;
        }

        float sfr[4][4] = {};
#pragma unroll 16
        for (int kk = 0; kk < 64; kk++) {
            float4 a = *(const float4*)&Qs[kk][4 * ty];
            float4 bb = *(const float4*)&Ks[kk][4 * tx];
            float av[4] = {a.x, a.y, a.z, a.w};
            float bv[4] = {bb.x, bb.y, bb.z, bb.w};
#pragma unroll
            for (int i = 0; i < 4; i++)
#pragma unroll
                for (int j = 0; j < 4; j++) sfr[i][j] += av[i] * bv[j];
        }
#pragma unroll
        for (int i = 0; i < 4; i++)
#pragma unroll
            for (int j = 0; j < 4; j++) {
                const float sc = sfr[i][j] * SCL + madd[4 * tx + j];
                acc[i][j] += (sc <= NEGBIG) ? 0.f : expf(sc - mrow[i]) * zinv[i];
            }
    }

#pragma unroll
    for (int i = 0; i < 4; i++) {
        const int qq = q0 + 4 * ty + i;
        float4 o4 = make_float4(acc[i][0] * 0.125f, acc[i][1] * 0.125f,
                                acc[i][2] * 0.125f, acc[i][3] * 0.125f);
        *(float4*)&out[((size_t)b * NS + qq) * NS + k0 + 4 * tx] = o4;
    }
}

// ---------------------------------------------------------------------------
extern "C" void kernel_launch(void* const* d_in, const int* in_sizes, int n_in,
                              void* d_out, int out_size) {
    // Identify inputs BY SIZE (robust to whether scalar num_heads is a buffer):
    //  4194304 -> query, key, value (in order)
    //  8192    -> mask
    //  262144  -> Wq, Wk, Wv, Wo (in order)
    //  512     -> bq, bk, bv, bo (in order)
    const float* qkv[3] = {0, 0, 0};
    const float* Ws[4] = {0, 0, 0, 0};
    const float* bs[4] = {0, 0, 0, 0};
    const void* maskraw = 0;
    int nqkv = 0, nW = 0, nb = 0;
    for (int i = 0; i < n_in; i++) {
        const int sz = in_sizes[i];
        if (sz == NB * NS * ND) { if (nqkv < 3) qkv[nqkv++] = (const float*)d_in[i]; }
        else if (sz == ND * ND) { if (nW < 4) Ws[nW++] = (const float*)d_in[i]; }
        else if (sz == ND)      { if (nb < 4) bs[nb++] = (const float*)d_in[i]; }
        else if (sz == NB * NS) { maskraw = d_in[i]; }
    }
    const float* query = qkv[0];
    const float* key   = qkv[1];
    const float* value = qkv[2];
    const float *Wq = Ws[0], *Wk = Ws[1], *Wv = Ws[2], *Wo = Ws[3];
    const float *bq = bs[0], *bk = bs[1], *bv = bs[2], *bo = bs[3];
    float* out = (float*)d_out;

    float *gQ, *gK, *gV, *gC, *gM, *gZ, *gMadd;
    cudaGetSymbolAddress((void**)&gQ, g_Q);
    cudaGetSymbolAddress((void**)&gK, g_K);
    cudaGetSymbolAddress((void**)&gV, g_V);
    cudaGetSymbolAddress((void**)&gC, g_Ctx);
    cudaGetSymbolAddress((void**)&gM, g_M);
    cudaGetSymbolAddress((void**)&gZ, g_Z);
    cudaGetSymbolAddress((void**)&gMadd, g_madd);

    // Canonicalize the mask to float 0/-inf (dtype sniffed on device)
    mask_detect<<<1, 256>>>((const unsigned char*)maskraw);
    mask_convert<<<(NB * NS + 255) / 256, 256>>>(maskraw);

    const dim3 blk(256);
    const dim3 gproj(ND / 64, (NB * NS) / 64);

    gemm_xwt<0><<<gproj, blk>>>(query, Wq, bq, gQ);
    gemm_xwt<0><<<gproj, blk>>>(key,   Wk, bk, gK);
    gemm_xwt<0><<<gproj, blk>>>(value, Wv, bv, gV);

    const size_t FLASH_SMEM = 4 * 64 * 68 * sizeof(float);
    cudaFuncSetAttribute(flash_attn, cudaFuncAttributeMaxDynamicSharedMemorySize,
                         (int)FLASH_SMEM);
    flash_attn<<<dim3(NS / 64, NB * NH), blk, FLASH_SMEM>>>(gMadd, gQ, gK, gV, gC, gM, gZ);

    gemm_xwt<1><<<gproj, blk>>>(gC, Wo, bo, out);

    const long long need = (long long)NB * NS * ND + (long long)NB * NS * NS;
    if ((long long)out_size >= need) {
        attn_mean_k<<<dim3(NS / 64, NS / 64, NB), blk>>>(
            gMadd, gQ, gK, gM, gZ, out + (size_t)NB * NS * ND);
    }
}

// round 3
// speedup vs baseline: 1.1364x; 1.1364x over previous
#include <cuda_runtime.h>
#include <math.h>

#define NB 4
#define NS 2048
#define ND 512
#define NH 8
#define NDK 64
#define SCL 0.125f
#define NEGBIG (-1e30f)

// Scratch
__device__ float g_Q[(size_t)NB * NH * NS * NDK];
__device__ float g_K[(size_t)NB * NH * NS * NDK];
__device__ float g_V[(size_t)NB * NH * NS * NDK];
__device__ float g_Ctx[(size_t)NB * NS * ND];
__device__ float g_M[(size_t)NB * NH * NS];
__device__ float g_Z[(size_t)NB * NH * NS];
__device__ float g_madd[(size_t)NB * NS];
__device__ int   g_maskkind;

// swizzled [d][vec128] layout: phys float index for the 4-aligned group 'g' in row d
__device__ __forceinline__ int SW(int d, int g) {
    return d * 128 + (((g) ^ ((d >> 2) & 7)) << 2);
}

// ---------------- mask sniff / convert (validated in R2) ----------------
__global__ void mask_detect(const unsigned char* __restrict__ mraw) {
    __shared__ int s_not01, s_oneOther, s_3fOdd;
    if (threadIdx.x == 0) { s_not01 = 0; s_oneOther = 0; s_3fOdd = 0; }
    __syncthreads();
    int l_not01 = 0, l_oneOther = 0, l_3fOdd = 0;
    for (int i = threadIdx.x; i < NB * NS; i += blockDim.x) {
        const unsigned char v = mraw[i];
        if (v > 1) l_not01++;
        if (v == 1 && (i & 3) != 0) l_oneOther++;
        if (v == 0x3f && (i & 3) == 1) l_3fOdd++;
    }
    atomicAdd(&s_not01, l_not01);
    atomicAdd(&s_oneOther, l_oneOther);
    atomicAdd(&s_3fOdd, l_3fOdd);
    __syncthreads();
    if (threadIdx.x == 0) {
        int kind;
        if (s_not01 > 0)        kind = (s_3fOdd > 0) ? 3 : 2;
        else if (s_oneOther == 0) kind = 1;
        else                    kind = 0;
        g_maskkind = kind;
    }
}

__global__ void mask_convert(const void* __restrict__ mraw) {
    const int i = blockIdx.x * blockDim.x + threadIdx.x;
    if (i >= NB * NS) return;
    const int kind = g_maskkind;
    bool on;
    if (kind == 0)      on = ((const unsigned char*)mraw)[i] != 0;
    else if (kind == 1) on = ((const int*)mraw)[i] != 0;
    else if (kind == 2) on = ((const float*)mraw)[i] != 0.f;
    else                on = ((const unsigned short*)mraw)[i] != 0;
    g_madd[i] = on ? 0.f : -INFINITY;
}

// ---------------------------------------------------------------------------
// GEMM: C[m,n] = sum_k X[m,k]*W[n,k] + bias[n].  128x128 tile, 8x8 micro.
// MODE 0: head-split write [b,h,s,dk]; MODE 1: flat.
// ---------------------------------------------------------------------------
template <int MODE>
__global__ __launch_bounds__(256) void gemm_xwt(const float* __restrict__ X,
                                                const float* __restrict__ W,
                                                const float* __restrict__ bias,
                                                float* __restrict__ Y) {
    __shared__ float As[16 * 128];
    __shared__ float Bs[16 * 128];
    const int tid = threadIdx.x;
    const int tx = tid & 15, ty = tid >> 4;
    const int m0 = blockIdx.y * 128, n0 = blockIdx.x * 128;
    const int lc = tid & 3, lr = tid >> 2;   // loader: 4 f4-cols x 64 rows

    float acc[8][8] = {};
    for (int k0 = 0; k0 < ND; k0 += 16) {
#pragma unroll
        for (int p = 0; p < 2; p++) {
            const int row = lr + 64 * p;
            const int qg = row >> 2, qr = row & 3;
            float4 xa = *(const float4*)&X[(size_t)(m0 + row) * ND + k0 + 4 * lc];
            float4 wb = *(const float4*)&W[(size_t)(n0 + row) * ND + k0 + 4 * lc];
            const int gi = (qg ^ lc) << 2;
            As[(4 * lc + 0) * 128 + gi + qr] = xa.x;
            As[(4 * lc + 1) * 128 + gi + qr] = xa.y;
            As[(4 * lc + 2) * 128 + gi + qr] = xa.z;
            As[(4 * lc + 3) * 128 + gi + qr] = xa.w;
            Bs[(4 * lc + 0) * 128 + gi + qr] = wb.x;
            Bs[(4 * lc + 1) * 128 + gi + qr] = wb.y;
            Bs[(4 * lc + 2) * 128 + gi + qr] = wb.z;
            Bs[(4 * lc + 3) * 128 + gi + qr] = wb.w;
        }
        __syncthreads();
#pragma unroll 8
        for (int kk = 0; kk < 16; kk++) {
            const int sa = SW(kk, ty), sb = SW(kk, tx);
            float4 a0 = *(const float4*)&As[sa];
            float4 a1 = *(const float4*)&As[sa + 64];
            float4 b0 = *(const float4*)&Bs[sb];
            float4 b1 = *(const float4*)&Bs[sb + 64];
            float av[8] = {a0.x, a0.y, a0.z, a0.w, a1.x, a1.y, a1.z, a1.w};
            float bv[8] = {b0.x, b0.y, b0.z, b0.w, b1.x, b1.y, b1.z, b1.w};
#pragma unroll
            for (int i = 0; i < 8; i++)
#pragma unroll
                for (int j = 0; j < 8; j++) acc[i][j] += av[i] * bv[j];
        }
        __syncthreads();
    }

    float4 bA = *(const float4*)&bias[n0 + 4 * tx];
    float4 bB = *(const float4*)&bias[n0 + 64 + 4 * tx];
#pragma unroll
    for (int i = 0; i < 8; i++) {
        const int m = m0 + ((i < 4) ? (4 * ty + i) : (64 + 4 * ty + i - 4));
        float4 vA = make_float4(acc[i][0] + bA.x, acc[i][1] + bA.y,
                                acc[i][2] + bA.z, acc[i][3] + bA.w);
        float4 vB = make_float4(acc[i][4] + bB.x, acc[i][5] + bB.y,
                                acc[i][6] + bB.z, acc[i][7] + bB.w);
        if (MODE == 0) {
            const int b = m >> 11, s = m & (NS - 1);
            const int hA = n0 >> 6, hB = hA + 1;
            *(float4*)&Y[(((size_t)(b * NH + hA)) * NS + s) * NDK + 4 * tx] = vA;
            *(float4*)&Y[(((size_t)(b * NH + hB)) * NS + s) * NDK + 4 * tx] = vB;
        } else {
            *(float4*)&Y[(size_t)m * ND + n0 + 4 * tx] = vA;
            *(float4*)&Y[(size_t)m * ND + n0 + 64 + 4 * tx] = vB;
        }
    }
}

// ---------------------------------------------------------------------------
// Flash attention: 128q x 128k tiles, 8x8 micro for QK^T, 8x4 for PV.
// ---------------------------------------------------------------------------
__global__ __launch_bounds__(256) void flash_attn(const float* __restrict__ maddg,
                                                  const float* __restrict__ Qg,
                                                  const float* __restrict__ Kg,
                                                  const float* __restrict__ Vg,
                                                  float* __restrict__ Og,
                                                  float* __restrict__ Mg,
                                                  float* __restrict__ Zg) {
    extern __shared__ float sm[];
    float* Qs = sm;                 // 64*128 swizzled [d][q]
    float* Ks = Qs + 64 * 128;      // 64*128 swizzled [d][k]
    float* Vs = Ks + 64 * 128;      // [k][d] 128*68
    float* Ps = Vs + 128 * 68;      // [q][k] 128*132
    float* madd = Ps + 128 * 132;   // 128

    const int tid = threadIdx.x;
    const int tx = tid & 15, ty = tid >> 4;
    const int bh = blockIdx.y;
    const int b = bh >> 3;
    const int h = bh & 7;
    const int q0 = blockIdx.x * 128;
    const float* Q = Qg + (size_t)bh * NS * NDK;
    const float* K = Kg + (size_t)bh * NS * NDK;
    const float* V = Vg + (size_t)bh * NS * NDK;

    const int lc = tid & 15, lr = tid >> 4;  // loader: 16 f4-cols x 16 rows
    {   // Q tile -> swizzled transpose
#pragma unroll
        for (int p = 0; p < 8; p++) {
            const int row = lr + 16 * p;
            float4 v = *(const float4*)&Q[(size_t)(q0 + row) * NDK + 4 * lc];
            const int gi = ((row >> 2) ^ (lc & 7)) << 2, qr = row & 3;
            Qs[(4 * lc + 0) * 128 + gi + qr] = v.x;
            Qs[(4 * lc + 1) * 128 + gi + qr] = v.y;
            Qs[(4 * lc + 2) * 128 + gi + qr] = v.z;
            Qs[(4 * lc + 3) * 128 + gi + qr] = v.w;
        }
    }

    float O[8][4] = {};
    float mI[8], zI[8];
#pragma unroll
    for (int i = 0; i < 8; i++) { mI[i] = -INFINITY; zI[i] = 0.f; }
    int qloc[8], qoff[8];
#pragma unroll
    for (int i = 0; i < 8; i++) {
        qloc[i] = (i < 4) ? (4 * ty + i) : (64 + 4 * ty + i - 4);
        qoff[i] = qloc[i] * 132;
    }
    __syncthreads();

    for (int kt = 0; kt < NS; kt += 128) {
        {   // K (swizzled transpose), V (natural), mask
#pragma unroll
            for (int p = 0; p < 8; p++) {
                const int row = lr + 16 * p;
                float4 kv = *(const float4*)&K[(size_t)(kt + row) * NDK + 4 * lc];
                float4 vv = *(const float4*)&V[(size_t)(kt + row) * NDK + 4 * lc];
                const int gi = ((row >> 2) ^ (lc & 7)) << 2, qr = row & 3;
                Ks[(4 * lc + 0) * 128 + gi + qr] = kv.x;
                Ks[(4 * lc + 1) * 128 + gi + qr] = kv.y;
                Ks[(4 * lc + 2) * 128 + gi + qr] = kv.z;
                Ks[(4 * lc + 3) * 128 + gi + qr] = kv.w;
                *(float4*)&Vs[row * 68 + 4 * lc] = vv;
            }
            if (tid < 128) madd[tid] = maddg[b * NS + kt + tid];
        }
        __syncthreads();

        // ---- S = Q K^T ----
        float s[8][8] = {};
#pragma unroll 8
        for (int dd = 0; dd < 64; dd++) {
            const int sa = SW(dd, ty), sb = SW(dd, tx);
            float4 a0 = *(const float4*)&Qs[sa];
            float4 a1 = *(const float4*)&Qs[sa + 64];
            float4 b0 = *(const float4*)&Ks[sb];
            float4 b1 = *(const float4*)&Ks[sb + 64];
            float av[8] = {a0.x, a0.y, a0.z, a0.w, a1.x, a1.y, a1.z, a1.w};
            float bv[8] = {b0.x, b0.y, b0.z, b0.w, b1.x, b1.y, b1.z, b1.w};
#pragma unroll
            for (int i = 0; i < 8; i++)
#pragma unroll
                for (int j = 0; j < 8; j++) s[i][j] += av[i] * bv[j];
        }

        // ---- online softmax (rows reduce over 16 tx lanes) ----
        float mk0 = madd[4 * tx + 0], mk1 = madd[4 * tx + 1];
        float mk2 = madd[4 * tx + 2], mk3 = madd[4 * tx + 3];
        float mk4 = madd[64 + 4 * tx + 0], mk5 = madd[64 + 4 * tx + 1];
        float mk6 = madd[64 + 4 * tx + 2], mk7 = madd[64 + 4 * tx + 3];
#pragma unroll
        for (int i = 0; i < 8; i++) {
            float sc[8];
            sc[0] = s[i][0] * SCL + mk0; sc[1] = s[i][1] * SCL + mk1;
            sc[2] = s[i][2] * SCL + mk2; sc[3] = s[i][3] * SCL + mk3;
            sc[4] = s[i][4] * SCL + mk4; sc[5] = s[i][5] * SCL + mk5;
            sc[6] = s[i][6] * SCL + mk6; sc[7] = s[i][7] * SCL + mk7;
            float rm = sc[0];
#pragma unroll
            for (int j = 1; j < 8; j++) rm = fmaxf(rm, sc[j]);
#pragma unroll
            for (int off = 8; off > 0; off >>= 1)
                rm = fmaxf(rm, __shfl_xor_sync(0xffffffffu, rm, off));
            const float mn = fmaxf(mI[i], rm);
            const float alpha = (mI[i] <= NEGBIG) ? 0.f : __expf(mI[i] - mn);
            float pv[8], rs = 0.f;
#pragma unroll
            for (int j = 0; j < 8; j++) {
                const float p = (sc[j] <= NEGBIG) ? 0.f : __expf(sc[j] - mn);
                pv[j] = p; rs += p;
            }
#pragma unroll
            for (int off = 8; off > 0; off >>= 1)
                rs += __shfl_xor_sync(0xffffffffu, rs, off);
            zI[i] = zI[i] * alpha + rs;
            mI[i] = mn;
#pragma unroll
            for (int j = 0; j < 4; j++) O[i][j] *= alpha;
            *(float4*)&Ps[qoff[i] + 4 * tx] = make_float4(pv[0], pv[1], pv[2], pv[3]);
            *(float4*)&Ps[qoff[i] + 64 + 4 * tx] = make_float4(pv[4], pv[5], pv[6], pv[7]);
        }
        __syncthreads();

        // ---- O += P V ----
#pragma unroll 8
        for (int kk = 0; kk < 128; kk++) {
            float4 v4 = *(const float4*)&Vs[kk * 68 + 4 * tx];
#pragma unroll
            for (int i = 0; i < 8; i++) {
                const float p = Ps[qoff[i] + kk];
                O[i][0] += p * v4.x;
                O[i][1] += p * v4.y;
                O[i][2] += p * v4.z;
                O[i][3] += p * v4.w;
            }
        }
        __syncthreads();
    }

    // epilogue
#pragma unroll
    for (int i = 0; i < 8; i++) {
        const float inv = (zI[i] > 0.f) ? 1.f / zI[i] : 0.f;
        const int qq = q0 + qloc[i];
        float4 o4 = make_float4(O[i][0] * inv, O[i][1] * inv, O[i][2] * inv, O[i][3] * inv);
        *(float4*)&Og[((size_t)(b * NS + qq)) * ND + h * NDK + 4 * tx] = o4;
        if (tx == 0) {
            Mg[(size_t)bh * NS + qq] = mI[i];
            Zg[(size_t)bh * NS + qq] = zI[i];
        }
    }
}

// ---------------------------------------------------------------------------
// attn.mean over heads: recompute S per (b, q-tile, k-tile) looping heads.
// ---------------------------------------------------------------------------
__global__ __launch_bounds__(256) void attn_mean_k(const float* __restrict__ maddg,
                                                   const float* __restrict__ Qg,
                                                   const float* __restrict__ Kg,
                                                   const float* __restrict__ Mg,
                                                   const float* __restrict__ Zg,
                                                   float* __restrict__ out) {
    extern __shared__ float sm2[];
    float* Qs = sm2;             // 64*128
    float* Ks = Qs + 64 * 128;   // 64*128
    float* madd = Ks + 64 * 128; // 128

    const int tid = threadIdx.x;
    const int tx = tid & 15, ty = tid >> 4;
    const int b = blockIdx.z;
    const int q0 = blockIdx.y * 128, k0 = blockIdx.x * 128;
    const int lc = tid & 15, lr = tid >> 4;
    if (tid < 128) madd[tid] = maddg[b * NS + k0 + tid];

    int qloc[8];
#pragma unroll
    for (int i = 0; i < 8; i++) qloc[i] = (i < 4) ? (4 * ty + i) : (64 + 4 * ty + i - 4);

    float acc[8][8] = {};
    for (int hh = 0; hh < NH; hh++) {
        __syncthreads();
        const float* Q = Qg + ((size_t)(b * NH + hh)) * NS * NDK;
        const float* K = Kg + ((size_t)(b * NH + hh)) * NS * NDK;
#pragma unroll
        for (int p = 0; p < 8; p++) {
            const int row = lr + 16 * p;
            float4 qv = *(const float4*)&Q[(size_t)(q0 + row) * NDK + 4 * lc];
            float4 kv = *(const float4*)&K[(size_t)(k0 + row) * NDK + 4 * lc];
            const int gi = ((row >> 2) ^ (lc & 7)) << 2, qr = row & 3;
            Qs[(4 * lc + 0) * 128 + gi + qr] = qv.x;
            Qs[(4 * lc + 1) * 128 + gi + qr] = qv.y;
            Qs[(4 * lc + 2) * 128 + gi + qr] = qv.z;
            Qs[(4 * lc + 3) * 128 + gi + qr] = qv.w;
            Ks[(4 * lc + 0) * 128 + gi + qr] = kv.x;
            Ks[(4 * lc + 1) * 128 + gi + qr] = kv.y;
            Ks[(4 * lc + 2) * 128 + gi + qr] = kv.z;
            Ks[(4 * lc + 3) * 128 + gi + qr] = kv.w;
        }
        __syncthreads();

        float mrow[8], zinv[8];
#pragma unroll
        for (int i = 0; i < 8; i++) {
            const size_t idx = ((size_t)(b * NH + hh)) * NS + q0 + qloc[i];
            mrow[i] = Mg[idx];
            const float z = Zg[idx];
            zinv[i] = (z > 0.f) ? 1.f / z : 0.f;
        }

        float s[8][8] = {};
#pragma unroll 8
        for (int dd = 0; dd < 64; dd++) {
            const int sa = SW(dd, ty), sb = SW(dd, tx);
            float4 a0 = *(const float4*)&Qs[sa];
            float4 a1 = *(const float4*)&Qs[sa + 64];
            float4 b0 = *(const float4*)&Ks[sb];
            float4 b1 = *(const float4*)&Ks[sb + 64];
            float av[8] = {a0.x, a0.y, a0.z, a0.w, a1.x, a1.y, a1.z, a1.w};
            float bv[8] = {b0.x, b0.y, b0.z, b0.w, b1.x, b1.y, b1.z, b1.w};
#pragma unroll
            for (int i = 0; i < 8; i++)
#pragma unroll
                for (int j = 0; j < 8; j++) s[i][j] += av[i] * bv[j];
        }
#pragma unroll
        for (int i = 0; i < 8; i++)
#pragma unroll
            for (int j = 0; j < 8; j++) {
                const int kk = (j < 4) ? (4 * tx + j) : (64 + 4 * tx + j - 4);
                const float sc = s[i][j] * SCL + madd[kk];
                acc[i][j] += (sc <= NEGBIG) ? 0.f : __expf(sc - mrow[i]) * zinv[i];
            }
    }

#pragma unroll
    for (int i = 0; i < 8; i++) {
        const int qq = q0 + qloc[i];
        float4 oA = make_float4(acc[i][0] * 0.125f, acc[i][1] * 0.125f,
                                acc[i][2] * 0.125f, acc[i][3] * 0.125f);
        float4 oB = make_float4(acc[i][4] * 0.125f, acc[i][5] * 0.125f,
                                acc[i][6] * 0.125f, acc[i][7] * 0.125f);
        *(float4*)&out[((size_t)b * NS + qq) * NS + k0 + 4 * tx] = oA;
        *(float4*)&out[((size_t)b * NS + qq) * NS + k0 + 64 + 4 * tx] = oB;
    }
}

// ---------------------------------------------------------------------------
extern "C" void kernel_launch(void* const* d_in, const int* in_sizes, int n_in,
                              void* d_out, int out_size) {
    const float* qkv[3] = {0, 0, 0};
    const float* Ws[4] = {0, 0, 0, 0};
    const float* bs[4] = {0, 0, 0, 0};
    const void* maskraw = 0;
    int nqkv = 0, nW = 0, nb = 0;
    for (int i = 0; i < n_in; i++) {
        const int sz = in_sizes[i];
        if (sz == NB * NS * ND) { if (nqkv < 3) qkv[nqkv++] = (const float*)d_in[i]; }
        else if (sz == ND * ND) { if (nW < 4) Ws[nW++] = (const float*)d_in[i]; }
        else if (sz == ND)      { if (nb < 4) bs[nb++] = (const float*)d_in[i]; }
        else if (sz == NB * NS) { maskraw = d_in[i]; }
    }
    float* out = (float*)d_out;

    float *gQ, *gK, *gV, *gC, *gM, *gZ, *gMadd;
    cudaGetSymbolAddress((void**)&gQ, g_Q);
    cudaGetSymbolAddress((void**)&gK, g_K);
    cudaGetSymbolAddress((void**)&gV, g_V);
    cudaGetSymbolAddress((void**)&gC, g_Ctx);
    cudaGetSymbolAddress((void**)&gM, g_M);
    cudaGetSymbolAddress((void**)&gZ, g_Z);
    cudaGetSymbolAddress((void**)&gMadd, g_madd);

    mask_detect<<<1, 256>>>((const unsigned char*)maskraw);
    mask_convert<<<(NB * NS + 255) / 256, 256>>>(maskraw);

    const dim3 blk(256);
    const dim3 gproj(ND / 128, (NB * NS) / 128);

    gemm_xwt<0><<<gproj, blk>>>(qkv[0], Ws[0], bs[0], gQ);
    gemm_xwt<0><<<gproj, blk>>>(qkv[1], Ws[1], bs[1], gK);
    gemm_xwt<0><<<gproj, blk>>>(qkv[2], Ws[2], bs[2], gV);

    const size_t FLASH_SMEM = (size_t)(64 * 128 * 2 + 128 * 68 + 128 * 132 + 128) * sizeof(float);
    static int cfg_done = 0;
    cudaFuncSetAttribute(flash_attn, cudaFuncAttributeMaxDynamicSharedMemorySize,
                         (int)FLASH_SMEM);
    flash_attn<<<dim3(NS / 128, NB * NH), blk, FLASH_SMEM>>>(gMadd, gQ, gK, gV, gC, gM, gZ);

    gemm_xwt<1><<<gproj, blk>>>(gC, Ws[3], bs[3], out);

    const size_t MEAN_SMEM = (size_t)(64 * 128 * 2 + 128) * sizeof(float);
    cudaFuncSetAttribute(attn_mean_k, cudaFuncAttributeMaxDynamicSharedMemorySize,
                         (int)MEAN_SMEM);
    const long long need = (long long)NB * NS * ND + (long long)NB * NS * NS;
    if ((long long)out_size >= need) {
        attn_mean_k<<<dim3(NS / 128, NS / 128, NB), blk, MEAN_SMEM>>>(
            gMadd, gQ, gK, gM, gZ, out + (size_t)NB * NS * ND);
    }
    (void)cfg_done;
}

// round 4
// speedup vs baseline: 1.1930x; 1.0498x over previous
#include <cuda_runtime.h>
#include <math.h>

#define NB 4
#define NS 2048
#define ND 512
#define NH 8
#define NDK 64
#define SCL 0.125f
#define NEGBIG (-1e30f)

typedef unsigned long long ull;

// Scratch
__device__ float g_Q[(size_t)NB * NH * NS * NDK];
__device__ float g_K[(size_t)NB * NH * NS * NDK];
__device__ float g_V[(size_t)NB * NH * NS * NDK];
__device__ float g_Ctx[(size_t)NB * NS * ND];
__device__ float g_M[(size_t)NB * NH * NS];
__device__ float g_Z[(size_t)NB * NH * NS];
__device__ float g_madd[(size_t)NB * NS];
__device__ int   g_maskkind;

// ---- packed f32x2 helpers (FFMA2 only reachable via PTX) ----
__device__ __forceinline__ ull pk2(float lo, float hi) {
    ull r; asm("mov.b64 %0, {%1, %2};" : "=l"(r) : "f"(lo), "f"(hi)); return r;
}
__device__ __forceinline__ void upk2(ull v, float& lo, float& hi) {
    asm("mov.b64 {%0, %1}, %2;" : "=f"(lo), "=f"(hi) : "l"(v));
}
__device__ __forceinline__ ull ffma2(ull a, ull b, ull c) {
    ull d; asm("fma.rn.f32x2 %0, %1, %2, %3;" : "=l"(d) : "l"(a), "l"(b), "l"(c)); return d;
}
__device__ __forceinline__ ull fmul2(ull a, ull b) {
    ull d; asm("mul.rn.f32x2 %0, %1, %2;" : "=l"(d) : "l"(a), "l"(b)); return d;
}

// swizzled [d][vec128] layout
__device__ __forceinline__ int SW(int d, int g) {
    return d * 128 + (((g) ^ ((d >> 2) & 7)) << 2);
}

// ---------------- mask sniff / convert (validated) ----------------
__global__ void mask_detect(const unsigned char* __restrict__ mraw) {
    __shared__ int s_not01, s_oneOther, s_3fOdd;
    if (threadIdx.x == 0) { s_not01 = 0; s_oneOther = 0; s_3fOdd = 0; }
    __syncthreads();
    int l_not01 = 0, l_oneOther = 0, l_3fOdd = 0;
    for (int i = threadIdx.x; i < NB * NS; i += blockDim.x) {
        const unsigned char v = mraw[i];
        if (v > 1) l_not01++;
        if (v == 1 && (i & 3) != 0) l_oneOther++;
        if (v == 0x3f && (i & 3) == 1) l_3fOdd++;
    }
    atomicAdd(&s_not01, l_not01);
    atomicAdd(&s_oneOther, l_oneOther);
    atomicAdd(&s_3fOdd, l_3fOdd);
    __syncthreads();
    if (threadIdx.x == 0) {
        int kind;
        if (s_not01 > 0)        kind = (s_3fOdd > 0) ? 3 : 2;
        else if (s_oneOther == 0) kind = 1;
        else                    kind = 0;
        g_maskkind = kind;
    }
}

__global__ void mask_convert(const void* __restrict__ mraw) {
    const int i = blockIdx.x * blockDim.x + threadIdx.x;
    if (i >= NB * NS) return;
    const int kind = g_maskkind;
    bool on;
    if (kind == 0)      on = ((const unsigned char*)mraw)[i] != 0;
    else if (kind == 1) on = ((const int*)mraw)[i] != 0;
    else if (kind == 2) on = ((const float*)mraw)[i] != 0.f;
    else                on = ((const unsigned short*)mraw)[i] != 0;
    g_madd[i] = on ? 0.f : -INFINITY;
}

// ---------------------------------------------------------------------------
// GEMM: C[m,n] = sum_k X[m,k]*W[n,k] + bias[n]. 128x128 tile, 8x8 micro, FFMA2.
// ---------------------------------------------------------------------------
template <int MODE>
__global__ __launch_bounds__(256) void gemm_xwt(const float* __restrict__ X,
                                                const float* __restrict__ W,
                                                const float* __restrict__ bias,
                                                float* __restrict__ Y) {
    __shared__ float As[16 * 128];
    __shared__ float Bs[16 * 128];
    const int tid = threadIdx.x;
    const int tx = tid & 15, ty = tid >> 4;
    const int m0 = blockIdx.y * 128, n0 = blockIdx.x * 128;
    const int lc = tid & 3, lr = tid >> 2;

    ull acc2[4][8];
#pragma unroll
    for (int rp = 0; rp < 4; rp++)
#pragma unroll
        for (int j = 0; j < 8; j++) acc2[rp][j] = 0ull;

    for (int k0 = 0; k0 < ND; k0 += 16) {
#pragma unroll
        for (int p = 0; p < 2; p++) {
            const int row = lr + 64 * p;
            const int qg = row >> 2, qr = row & 3;
            float4 xa = *(const float4*)&X[(size_t)(m0 + row) * ND + k0 + 4 * lc];
            float4 wb = *(const float4*)&W[(size_t)(n0 + row) * ND + k0 + 4 * lc];
            const int gi = (qg ^ lc) << 2;
            As[(4 * lc + 0) * 128 + gi + qr] = xa.x;
            As[(4 * lc + 1) * 128 + gi + qr] = xa.y;
            As[(4 * lc + 2) * 128 + gi + qr] = xa.z;
            As[(4 * lc + 3) * 128 + gi + qr] = xa.w;
            Bs[(4 * lc + 0) * 128 + gi + qr] = wb.x;
            Bs[(4 * lc + 1) * 128 + gi + qr] = wb.y;
            Bs[(4 * lc + 2) * 128 + gi + qr] = wb.z;
            Bs[(4 * lc + 3) * 128 + gi + qr] = wb.w;
        }
        __syncthreads();
#pragma unroll 8
        for (int kk = 0; kk < 16; kk++) {
            const int sa = SW(kk, ty), sb = SW(kk, tx);
            float4 a0 = *(const float4*)&As[sa];
            float4 a1 = *(const float4*)&As[sa + 64];
            float4 b0 = *(const float4*)&Bs[sb];
            float4 b1 = *(const float4*)&Bs[sb + 64];
            ull ap[4] = {pk2(a0.x, a0.y), pk2(a0.z, a0.w),
                         pk2(a1.x, a1.y), pk2(a1.z, a1.w)};
            float bv[8] = {b0.x, b0.y, b0.z, b0.w, b1.x, b1.y, b1.z, b1.w};
#pragma unroll
            for (int j = 0; j < 8; j++) {
                const ull bd = pk2(bv[j], bv[j]);
#pragma unroll
                for (int rp = 0; rp < 4; rp++)
                    acc2[rp][j] = ffma2(ap[rp], bd, acc2[rp][j]);
            }
        }
        __syncthreads();
    }

    float acc[8][8];
#pragma unroll
    for (int rp = 0; rp < 4; rp++)
#pragma unroll
        for (int j = 0; j < 8; j++) upk2(acc2[rp][j], acc[2 * rp][j], acc[2 * rp + 1][j]);

    float4 bA = *(const float4*)&bias[n0 + 4 * tx];
    float4 bB = *(const float4*)&bias[n0 + 64 + 4 * tx];
#pragma unroll
    for (int i = 0; i < 8; i++) {
        const int m = m0 + ((i < 4) ? (4 * ty + i) : (64 + 4 * ty + i - 4));
        float4 vA = make_float4(acc[i][0] + bA.x, acc[i][1] + bA.y,
                                acc[i][2] + bA.z, acc[i][3] + bA.w);
        float4 vB = make_float4(acc[i][4] + bB.x, acc[i][5] + bB.y,
                                acc[i][6] + bB.z, acc[i][7] + bB.w);
        if (MODE == 0) {
            const int b = m >> 11, s = m & (NS - 1);
            const int hA = n0 >> 6, hB = hA + 1;
            *(float4*)&Y[(((size_t)(b * NH + hA)) * NS + s) * NDK + 4 * tx] = vA;
            *(float4*)&Y[(((size_t)(b * NH + hB)) * NS + s) * NDK + 4 * tx] = vB;
        } else {
            *(float4*)&Y[(size_t)m * ND + n0 + 4 * tx] = vA;
            *(float4*)&Y[(size_t)m * ND + n0 + 64 + 4 * tx] = vB;
        }
    }
}

// ---------------------------------------------------------------------------
// Flash attention: 128q x 128k tiles, FFMA2 QK^T and PV.
// ---------------------------------------------------------------------------
__global__ __launch_bounds__(256) void flash_attn(const float* __restrict__ maddg,
                                                  const float* __restrict__ Qg,
                                                  const float* __restrict__ Kg,
                                                  const float* __restrict__ Vg,
                                                  float* __restrict__ Og,
                                                  float* __restrict__ Mg,
                                                  float* __restrict__ Zg) {
    extern __shared__ float sm[];
    float* Qs = sm;
    float* Ks = Qs + 64 * 128;
    float* Vs = Ks + 64 * 128;
    float* Ps = Vs + 128 * 68;
    float* madd = Ps + 128 * 132;

    const int tid = threadIdx.x;
    const int tx = tid & 15, ty = tid >> 4;
    const int bh = blockIdx.y;
    const int b = bh >> 3;
    const int h = bh & 7;
    const int q0 = blockIdx.x * 128;
    const float* Q = Qg + (size_t)bh * NS * NDK;
    const float* K = Kg + (size_t)bh * NS * NDK;
    const float* V = Vg + (size_t)bh * NS * NDK;

    const int lc = tid & 15, lr = tid >> 4;
    {
#pragma unroll
        for (int p = 0; p < 8; p++) {
            const int row = lr + 16 * p;
            float4 v = *(const float4*)&Q[(size_t)(q0 + row) * NDK + 4 * lc];
            const int gi = ((row >> 2) ^ (lc & 7)) << 2, qr = row & 3;
            Qs[(4 * lc + 0) * 128 + gi + qr] = v.x;
            Qs[(4 * lc + 1) * 128 + gi + qr] = v.y;
            Qs[(4 * lc + 2) * 128 + gi + qr] = v.z;
            Qs[(4 * lc + 3) * 128 + gi + qr] = v.w;
        }
    }

    ull O2[8][2];
#pragma unroll
    for (int i = 0; i < 8; i++) { O2[i][0] = 0ull; O2[i][1] = 0ull; }
    float mI[8], zI[8];
#pragma unroll
    for (int i = 0; i < 8; i++) { mI[i] = -INFINITY; zI[i] = 0.f; }
    int qloc[8], qoff[8];
#pragma unroll
    for (int i = 0; i < 8; i++) {
        qloc[i] = (i < 4) ? (4 * ty + i) : (64 + 4 * ty + i - 4);
        qoff[i] = qloc[i] * 132;
    }
    __syncthreads();

    for (int kt = 0; kt < NS; kt += 128) {
        {
#pragma unroll
            for (int p = 0; p < 8; p++) {
                const int row = lr + 16 * p;
                float4 kv = *(const float4*)&K[(size_t)(kt + row) * NDK + 4 * lc];
                float4 vv = *(const float4*)&V[(size_t)(kt + row) * NDK + 4 * lc];
                const int gi = ((row >> 2) ^ (lc & 7)) << 2, qr = row & 3;
                Ks[(4 * lc + 0) * 128 + gi + qr] = kv.x;
                Ks[(4 * lc + 1) * 128 + gi + qr] = kv.y;
                Ks[(4 * lc + 2) * 128 + gi + qr] = kv.z;
                Ks[(4 * lc + 3) * 128 + gi + qr] = kv.w;
                *(float4*)&Vs[row * 68 + 4 * lc] = vv;
            }
            if (tid < 128) madd[tid] = maddg[b * NS + kt + tid];
        }
        __syncthreads();

        // ---- S = Q K^T (packed row-pairs) ----
        ull s2[4][8];
#pragma unroll
        for (int rp = 0; rp < 4; rp++)
#pragma unroll
            for (int j = 0; j < 8; j++) s2[rp][j] = 0ull;
#pragma unroll 8
        for (int dd = 0; dd < 64; dd++) {
            const int sa = SW(dd, ty), sb = SW(dd, tx);
            float4 a0 = *(const float4*)&Qs[sa];
            float4 a1 = *(const float4*)&Qs[sa + 64];
            float4 b0 = *(const float4*)&Ks[sb];
            float4 b1 = *(const float4*)&Ks[sb + 64];
            ull ap[4] = {pk2(a0.x, a0.y), pk2(a0.z, a0.w),
                         pk2(a1.x, a1.y), pk2(a1.z, a1.w)};
            float bv[8] = {b0.x, b0.y, b0.z, b0.w, b1.x, b1.y, b1.z, b1.w};
#pragma unroll
            for (int j = 0; j < 8; j++) {
                const ull bd = pk2(bv[j], bv[j]);
#pragma unroll
                for (int rp = 0; rp < 4; rp++)
                    s2[rp][j] = ffma2(ap[rp], bd, s2[rp][j]);
            }
        }
        float s[8][8];
#pragma unroll
        for (int rp = 0; rp < 4; rp++)
#pragma unroll
            for (int j = 0; j < 8; j++) upk2(s2[rp][j], s[2 * rp][j], s[2 * rp + 1][j]);

        // ---- online softmax ----
        float mk[8];
        mk[0] = madd[4 * tx + 0]; mk[1] = madd[4 * tx + 1];
        mk[2] = madd[4 * tx + 2]; mk[3] = madd[4 * tx + 3];
        mk[4] = madd[64 + 4 * tx + 0]; mk[5] = madd[64 + 4 * tx + 1];
        mk[6] = madd[64 + 4 * tx + 2]; mk[7] = madd[64 + 4 * tx + 3];
#pragma unroll
        for (int i = 0; i < 8; i++) {
            float sc[8];
#pragma unroll
            for (int j = 0; j < 8; j++) sc[j] = s[i][j] * SCL + mk[j];
            float rm = sc[0];
#pragma unroll
            for (int j = 1; j < 8; j++) rm = fmaxf(rm, sc[j]);
#pragma unroll
            for (int off = 8; off > 0; off >>= 1)
                rm = fmaxf(rm, __shfl_xor_sync(0xffffffffu, rm, off));
            const float mn = fmaxf(mI[i], rm);
            const float alpha = (mI[i] <= NEGBIG) ? 0.f : __expf(mI[i] - mn);
            float pv[8], rs = 0.f;
#pragma unroll
            for (int j = 0; j < 8; j++) {
                const float p = (sc[j] <= NEGBIG) ? 0.f : __expf(sc[j] - mn);
                pv[j] = p; rs += p;
            }
#pragma unroll
            for (int off = 8; off > 0; off >>= 1)
                rs += __shfl_xor_sync(0xffffffffu, rs, off);
            zI[i] = zI[i] * alpha + rs;
            mI[i] = mn;
            const ull ad = pk2(alpha, alpha);
            O2[i][0] = fmul2(O2[i][0], ad);
            O2[i][1] = fmul2(O2[i][1], ad);
            *(float4*)&Ps[qoff[i] + 4 * tx] = make_float4(pv[0], pv[1], pv[2], pv[3]);
            *(float4*)&Ps[qoff[i] + 64 + 4 * tx] = make_float4(pv[4], pv[5], pv[6], pv[7]);
        }
        __syncthreads();

        // ---- O += P V (packed column-pairs) ----
#pragma unroll 8
        for (int kk = 0; kk < 128; kk++) {
            float4 v4 = *(const float4*)&Vs[kk * 68 + 4 * tx];
            const ull vp0 = pk2(v4.x, v4.y), vp1 = pk2(v4.z, v4.w);
#pragma unroll
            for (int i = 0; i < 8; i++) {
                const float p = Ps[qoff[i] + kk];
                const ull pd = pk2(p, p);
                O2[i][0] = ffma2(pd, vp0, O2[i][0]);
                O2[i][1] = ffma2(pd, vp1, O2[i][1]);
            }
        }
        __syncthreads();
    }

    // epilogue
#pragma unroll
    for (int i = 0; i < 8; i++) {
        const float inv = (zI[i] > 0.f) ? 1.f / zI[i] : 0.f;
        const int qq = q0 + qloc[i];
        float o[4];
        upk2(O2[i][0], o[0], o[1]);
        upk2(O2[i][1], o[2], o[3]);
        float4 o4 = make_float4(o[0] * inv, o[1] * inv, o[2] * inv, o[3] * inv);
        *(float4*)&Og[((size_t)(b * NS + qq)) * ND + h * NDK + 4 * tx] = o4;
        if (tx == 0) {
            Mg[(size_t)bh * NS + qq] = mI[i];
            Zg[(size_t)bh * NS + qq] = zI[i];
        }
    }
}

// ---------------------------------------------------------------------------
// attn.mean over heads, FFMA2 QK^T.
// ---------------------------------------------------------------------------
__global__ __launch_bounds__(256) void attn_mean_k(const float* __restrict__ maddg,
                                                   const float* __restrict__ Qg,
                                                   const float* __restrict__ Kg,
                                                   const float* __restrict__ Mg,
                                                   const float* __restrict__ Zg,
                                                   float* __restrict__ out) {
    extern __shared__ float sm2[];
    float* Qs = sm2;
    float* Ks = Qs + 64 * 128;
    float* madd = Ks + 64 * 128;

    const int tid = threadIdx.x;
    const int tx = tid & 15, ty = tid >> 4;
    const int b = blockIdx.z;
    const int q0 = blockIdx.y * 128, k0 = blockIdx.x * 128;
    const int lc = tid & 15, lr = tid >> 4;
    if (tid < 128) madd[tid] = maddg[b * NS + k0 + tid];

    int qloc[8];
#pragma unroll
    for (int i = 0; i < 8; i++) qloc[i] = (i < 4) ? (4 * ty + i) : (64 + 4 * ty + i - 4);

    float acc[8][8] = {};
    for (int hh = 0; hh < NH; hh++) {
        __syncthreads();
        const float* Q = Qg + ((size_t)(b * NH + hh)) * NS * NDK;
        const float* K = Kg + ((size_t)(b * NH + hh)) * NS * NDK;
#pragma unroll
        for (int p = 0; p < 8; p++) {
            const int row = lr + 16 * p;
            float4 qv = *(const float4*)&Q[(size_t)(q0 + row) * NDK + 4 * lc];
            float4 kv = *(const float4*)&K[(size_t)(k0 + row) * NDK + 4 * lc];
            const int gi = ((row >> 2) ^ (lc & 7)) << 2, qr = row & 3;
            Qs[(4 * lc + 0) * 128 + gi + qr] = qv.x;
            Qs[(4 * lc + 1) * 128 + gi + qr] = qv.y;
            Qs[(4 * lc + 2) * 128 + gi + qr] = qv.z;
            Qs[(4 * lc + 3) * 128 + gi + qr] = qv.w;
            Ks[(4 * lc + 0) * 128 + gi + qr] = kv.x;
            Ks[(4 * lc + 1) * 128 + gi + qr] = kv.y;
            Ks[(4 * lc + 2) * 128 + gi + qr] = kv.z;
            Ks[(4 * lc + 3) * 128 + gi + qr] = kv.w;
        }
        __syncthreads();

        float mrow[8], zinv[8];
#pragma unroll
        for (int i = 0; i < 8; i++) {
            const size_t idx = ((size_t)(b * NH + hh)) * NS + q0 + qloc[i];
            mrow[i] = Mg[idx];
            const float z = Zg[idx];
            zinv[i] = (z > 0.f) ? 1.f / z : 0.f;
        }

        ull s2[4][8];
#pragma unroll
        for (int rp = 0; rp < 4; rp++)
#pragma unroll
            for (int j = 0; j < 8; j++) s2[rp][j] = 0ull;
#pragma unroll 8
        for (int dd = 0; dd < 64; dd++) {
            const int sa = SW(dd, ty), sb = SW(dd, tx);
            float4 a0 = *(const float4*)&Qs[sa];
            float4 a1 = *(const float4*)&Qs[sa + 64];
            float4 b0 = *(const float4*)&Ks[sb];
            float4 b1 = *(const float4*)&Ks[sb + 64];
            ull ap[4] = {pk2(a0.x, a0.y), pk2(a0.z, a0.w),
                         pk2(a1.x, a1.y), pk2(a1.z, a1.w)};
            float bv[8] = {b0.x, b0.y, b0.z, b0.w, b1.x, b1.y, b1.z, b1.w};
#pragma unroll
            for (int j = 0; j < 8; j++) {
                const ull bd = pk2(bv[j], bv[j]);
#pragma unroll
                for (int rp = 0; rp < 4; rp++)
                    s2[rp][j] = ffma2(ap[rp], bd, s2[rp][j]);
            }
        }
#pragma unroll
        for (int rp = 0; rp < 4; rp++)
#pragma unroll
            for (int j = 0; j < 8; j++) {
                float lo, hi;
                upk2(s2[rp][j], lo, hi);
                const int kkA = (j < 4) ? (4 * tx + j) : (64 + 4 * tx + j - 4);
                const float scLo = lo * SCL + madd[kkA];
                const float scHi = hi * SCL + madd[kkA];
                acc[2 * rp][j]     += (scLo <= NEGBIG) ? 0.f : __expf(scLo - mrow[2 * rp]) * zinv[2 * rp];
                acc[2 * rp + 1][j] += (scHi <= NEGBIG) ? 0.f : __expf(scHi - mrow[2 * rp + 1]) * zinv[2 * rp + 1];
            }
    }

#pragma unroll
    for (int i = 0; i < 8; i++) {
        const int qq = q0 + qloc[i];
        float4 oA = make_float4(acc[i][0] * 0.125f, acc[i][1] * 0.125f,
                                acc[i][2] * 0.125f, acc[i][3] * 0.125f);
        float4 oB = make_float4(acc[i][4] * 0.125f, acc[i][5] * 0.125f,
                                acc[i][6] * 0.125f, acc[i][7] * 0.125f);
        *(float4*)&out[((size_t)b * NS + qq) * NS + k0 + 4 * tx] = oA;
        *(float4*)&out[((size_t)b * NS + qq) * NS + k0 + 64 + 4 * tx] = oB;
    }
}

// ---------------------------------------------------------------------------
extern "C" void kernel_launch(void* const* d_in, const int* in_sizes, int n_in,
                              void* d_out, int out_size) {
    const float* qkv[3] = {0, 0, 0};
    const float* Ws[4] = {0, 0, 0, 0};
    const float* bs[4] = {0, 0, 0, 0};
    const void* maskraw = 0;
    int nqkv = 0, nW = 0, nb = 0;
    for (int i = 0; i < n_in; i++) {
        const int sz = in_sizes[i];
        if (sz == NB * NS * ND) { if (nqkv < 3) qkv[nqkv++] = (const float*)d_in[i]; }
        else if (sz == ND * ND) { if (nW < 4) Ws[nW++] = (const float*)d_in[i]; }
        else if (sz == ND)      { if (nb < 4) bs[nb++] = (const float*)d_in[i]; }
        else if (sz == NB * NS) { maskraw = d_in[i]; }
    }
    float* out = (float*)d_out;

    float *gQ, *gK, *gV, *gC, *gM, *gZ, *gMadd;
    cudaGetSymbolAddress((void**)&gQ, g_Q);
    cudaGetSymbolAddress((void**)&gK, g_K);
    cudaGetSymbolAddress((void**)&gV, g_V);
    cudaGetSymbolAddress((void**)&gC, g_Ctx);
    cudaGetSymbolAddress((void**)&gM, g_M);
    cudaGetSymbolAddress((void**)&gZ, g_Z);
    cudaGetSymbolAddress((void**)&gMadd, g_madd);

    mask_detect<<<1, 256>>>((const unsigned char*)maskraw);
    mask_convert<<<(NB * NS + 255) / 256, 256>>>(maskraw);

    const dim3 blk(256);
    const dim3 gproj(ND / 128, (NB * NS) / 128);

    gemm_xwt<0><<<gproj, blk>>>(qkv[0], Ws[0], bs[0], gQ);
    gemm_xwt<0><<<gproj, blk>>>(qkv[1], Ws[1], bs[1], gK);
    gemm_xwt<0><<<gproj, blk>>>(qkv[2], Ws[2], bs[2], gV);

    const size_t FLASH_SMEM = (size_t)(64 * 128 * 2 + 128 * 68 + 128 * 132 + 128) * sizeof(float);
    cudaFuncSetAttribute(flash_attn, cudaFuncAttributeMaxDynamicSharedMemorySize,
                         (int)FLASH_SMEM);
    flash_attn<<<dim3(NS / 128, NB * NH), blk, FLASH_SMEM>>>(gMadd, gQ, gK, gV, gC, gM, gZ);

    gemm_xwt<1><<<gproj, blk>>>(gC, Ws[3], bs[3], out);

    const size_t MEAN_SMEM = (size_t)(64 * 128 * 2 + 128) * sizeof(float);
    cudaFuncSetAttribute(attn_mean_k, cudaFuncAttributeMaxDynamicSharedMemorySize,
                         (int)MEAN_SMEM);
    const long long need = (long long)NB * NS * ND + (long long)NB * NS * NS;
    if ((long long)out_size >= need) {
        attn_mean_k<<<dim3(NS / 128, NS / 128, NB), blk, MEAN_SMEM>>>(
            gMadd, gQ, gK, gM, gZ, out + (size_t)NB * NS * ND);
    }
}